// round 12
// baseline (speedup 1.0000x reference)
#include <cuda_runtime.h>
#include <cuda_bf16.h>

#define BB 4
#define SS 2048
#define HH 2048
#define RR 64
#define KSPLIT 4
#define KPER (2048 / KSPLIT)   // 512 per CTA
#define NC (KPER / 32)         // 16 k-chunks of 32

// ---------------------------------------------------------------------------
// Global scratch (static device arrays; no runtime allocation).
// ---------------------------------------------------------------------------
__device__ __align__(16) unsigned short g_Wsh[RR * SS];
__device__ __align__(16) unsigned short g_Wsl[RR * SS];
__device__ __align__(16) unsigned short g_Whh[RR * HH];
__device__ __align__(16) unsigned short g_Whl[RR * HH];
__device__ __align__(16) unsigned short g_Fsh[BB * SS * RR];  // F_s [b][s][r]
__device__ __align__(16) unsigned short g_Fsl[BB * SS * RR];
__device__ __align__(16) unsigned short g_Fhh[BB * HH * RR];  // F_h [b][h][r]
__device__ __align__(16) unsigned short g_Fhl[BB * HH * RR];
// split-K fp32 partials: [gb(8)][tile(16)][ky(4)][128*64]  (16.8 MB)
__device__ __align__(16) float g_part[8 * 16 * KSPLIT * 128 * 64];

// ---------------------------------------------------------------------------
// Helpers (R7-proven forms: volatile MMA + volatile LDSM — the pinned
// schedule measurably beats ptxas's unconstrained one on this kernel, and
// LDSM volatility is required for correctness across the double buffer).
// ---------------------------------------------------------------------------
__device__ __forceinline__ unsigned pack2(float v0, float v1) {
    __nv_bfloat162 t = __floats2bfloat162_rn(v0, v1);
    return *reinterpret_cast<unsigned*>(&t);
}

__device__ __forceinline__ void split_pair(float v0, float v1, unsigned& h, unsigned& l) {
    h = pack2(v0, v1);
    float h0 = __uint_as_float(h << 16);
    float h1 = __uint_as_float(h & 0xFFFF0000u);
    l = pack2(v0 - h0, v1 - h1);
}

__device__ __forceinline__ void mma_bf16(float c[4], const unsigned a[4], const unsigned b[2]) {
    asm volatile(
        "mma.sync.aligned.m16n8k16.row.col.f32.bf16.bf16.f32 "
        "{%0,%1,%2,%3}, {%4,%5,%6,%7}, {%8,%9}, {%0,%1,%2,%3};\n"
        : "+f"(c[0]), "+f"(c[1]), "+f"(c[2]), "+f"(c[3])
        : "r"(a[0]), "r"(a[1]), "r"(a[2]), "r"(a[3]), "r"(b[0]), "r"(b[1]));
}

__device__ __forceinline__ void ldsm4(unsigned* r, unsigned a) {
    asm volatile("ldmatrix.sync.aligned.m8n8.x4.shared.b16 {%0,%1,%2,%3}, [%4];\n"
                 : "=r"(r[0]), "=r"(r[1]), "=r"(r[2]), "=r"(r[3]) : "r"(a));
}
__device__ __forceinline__ void ldsm4t(unsigned* r, unsigned a) {
    asm volatile("ldmatrix.sync.aligned.m8n8.x4.trans.shared.b16 {%0,%1,%2,%3}, [%4];\n"
                 : "=r"(r[0]), "=r"(r[1]), "=r"(r[2]), "=r"(r[3]) : "r"(a));
}

__device__ __forceinline__ void cp16(unsigned dst, const void* src) {
    asm volatile("cp.async.cg.shared.global [%0], [%1], 16;\n" :: "r"(dst), "l"(src));
}
__device__ __forceinline__ void cp_commit() { asm volatile("cp.async.commit_group;\n"); }
__device__ __forceinline__ void cp_wait1()  { asm volatile("cp.async.wait_group 1;\n" ::: "memory"); }
__device__ __forceinline__ void cp_wait0()  { asm volatile("cp.async.wait_group 0;\n" ::: "memory"); }

// ---------------------------------------------------------------------------
// Kernel 0: split the two small W matrices fp32 -> hi/lo bf16.
// ---------------------------------------------------------------------------
__global__ void __launch_bounds__(256) wsplit_kernel(const float4* __restrict__ Wseq,
                                                     const float4* __restrict__ Whid) {
    const bool second = blockIdx.x >= 64;
    const float4* src = second ? Whid : Wseq;
    uint2* dh = (uint2*)(second ? g_Whh : g_Wsh);
    uint2* dl = (uint2*)(second ? g_Whl : g_Wsl);
    const int n4 = RR * SS / 4;
    for (int i = (blockIdx.x & 63) * 256 + threadIdx.x; i < n4; i += 64 * 256) {
        float4 v = src[i];
        unsigned h0, l0, h1, l1;
        split_pair(v.x, v.y, h0, l0);
        split_pair(v.z, v.w, h1, l1);
        dh[i] = make_uint2(h0, h1);
        dl[i] = make_uint2(l0, l1);
    }
}

// ---------------------------------------------------------------------------
// Kernel 1: fused factor GEMMs, split-K, fused fp32->bf16 split of X.
// R7-exact core; ONLY change this round: minocc 2 -> 3 (smem 60KB x3 = 180KB
// fits; 69 regs < 84-reg cap, no spill).
// ---------------------------------------------------------------------------
#define AP1 40     // G1 A pitch (shorts): [m=128][k=32]
#define AP2 136    // G2 A pitch (shorts): [k=32][m=128]
#define BP  40     // B pitch: [n=64][k=32]
#define ABUF 5120
#define BBUF 2560
#define STG  (2 * ABUF + 2 * BBUF)       // 15360 shorts per stage
#define FSM_BYTES (2 * STG * 2)          // 61440 bytes (2 stages)

__global__ void __launch_bounds__(256, 3) fact_kernel(const float* __restrict__ X) {
    extern __shared__ unsigned short fsm[];
    const unsigned sbase = (unsigned)__cvta_generic_to_shared(fsm);

    const int b = blockIdx.z, ky = blockIdx.y, tid = threadIdx.x;
    const bool isG1 = (blockIdx.x < 16);
    const int tile = isG1 ? blockIdx.x : blockIdx.x - 16;
    const int m0 = tile * 128;
    const int kbase = ky * KPER;

    // ---- A source pointers (fp32 X), 4 x float4 per thread per chunk ----
    const float* pA[4];
    long astep;
    int sr[4], sc[4];
    if (isG1) {
#pragma unroll
        for (int p = 0; p < 4; ++p) {
            int idx = tid + p * 256;
            int row = idx >> 3, c4 = (idx & 7) * 4;
            pA[p] = X + ((long)(b * SS + m0 + row)) * HH + kbase + c4;
            sr[p] = row; sc[p] = c4;
        }
        astep = 32;
    } else {
#pragma unroll
        for (int p = 0; p < 4; ++p) {
            int idx = tid + p * 256;
            int kr = idx >> 5, c4 = (idx & 31) * 4;
            pA[p] = X + ((long)(b * SS + kbase + kr)) * HH + m0 + c4;
            sr[p] = kr; sc[p] = c4;
        }
        astep = (long)32 * HH;
    }
    const int APx = isG1 ? AP1 : AP2;

    // ---- B staging (cp.async) ----
    const unsigned short* Bh_src = isG1 ? g_Whh : g_Wsh;
    const unsigned short* Bl_src = isG1 ? g_Whl : g_Wsl;
    const int brow = tid >> 2, bc = (tid & 3) * 8;
    const long bsoff = (long)brow * (isG1 ? HH : SS) + kbase + bc;
    const unsigned bdst = (unsigned)((2 * ABUF + brow * BP + bc) * 2);

    auto issueB = [&](int kc, int s) {
        const unsigned base = sbase + (unsigned)(s * STG * 2) + bdst;
        const long off = bsoff + kc * 32;
        cp16(base, Bh_src + off);
        cp16(base + BBUF * 2, Bl_src + off);
    };

    float4 pa[4];
#pragma unroll
    for (int p = 0; p < 4; ++p) pa[p] = *(const float4*)pA[p];
    issueB(0, 0); cp_commit();

    const int warpId = tid >> 5, lane = tid & 31;
    const int mB = (warpId >> 1) * 32, nB = (warpId & 1) * 32;

    const unsigned aoff1 = (unsigned)(((mB + (lane & 15)) * AP1 + (lane >> 4) * 8) * 2);
    const unsigned aoff2 = (unsigned)(((((lane & 7) + ((lane & 16) >> 1)) * AP2) +
                                       mB + ((lane >> 3) & 1) * 8) * 2);
    const unsigned boff  = (unsigned)(((nB + (lane & 7) + ((lane & 16) >> 1)) * BP +
                                       (lane & 8)) * 2);

    float acc[2][4][4];
#pragma unroll
    for (int i = 0; i < 2; ++i)
#pragma unroll
        for (int j = 0; j < 4; ++j)
#pragma unroll
            for (int t = 0; t < 4; ++t) acc[i][j][t] = 0.0f;

#pragma unroll 1
    for (int kc = 0; kc < NC; ++kc) {
        const unsigned base = sbase + (unsigned)((kc & 1) * STG * 2);
        const unsigned bAh = base, bAl = base + ABUF * 2;
        const unsigned bBh = base + 2 * ABUF * 2, bBl = bBh + BBUF * 2;

        unsigned short* Ahp = fsm + (kc & 1) * STG;
        unsigned short* Alp = Ahp + ABUF;
#pragma unroll
        for (int p = 0; p < 4; ++p) {
            unsigned h0, l0, h1, l1;
            split_pair(pa[p].x, pa[p].y, h0, l0);
            split_pair(pa[p].z, pa[p].w, h1, l1);
            int o = sr[p] * APx + sc[p];
            *(uint2*)&Ahp[o] = make_uint2(h0, h1);
            *(uint2*)&Alp[o] = make_uint2(l0, l1);
        }
        cp_wait0();
        __syncthreads();

        if (kc + 1 < NC) {
            issueB(kc + 1, (kc + 1) & 1); cp_commit();
#pragma unroll
            for (int p = 0; p < 4; ++p) {
                pA[p] += astep;
                pa[p] = *(const float4*)pA[p];
            }
        }

#pragma unroll
        for (int kb = 0; kb < 32; kb += 16) {
            unsigned bhf[2][4], blf[2][4];
            ldsm4(bhf[0], bBh + boff + kb * 2);
            ldsm4(bhf[1], bBh + boff + kb * 2 + 16 * BP * 2);
            ldsm4(blf[0], bBl + boff + kb * 2);
            ldsm4(blf[1], bBl + boff + kb * 2 + 16 * BP * 2);
#pragma unroll
            for (int i = 0; i < 2; ++i) {
                unsigned ah[4], al[4];
                if (isG1) {
                    unsigned o = aoff1 + (unsigned)(i * 16 * AP1 * 2 + kb * 2);
                    ldsm4(ah, bAh + o);
                    ldsm4(al, bAl + o);
                } else {
                    unsigned o = aoff2 + (unsigned)(kb * AP2 * 2 + i * 16 * 2);
                    ldsm4t(ah, bAh + o);
                    ldsm4t(al, bAl + o);
                }
#pragma unroll
                for (int j = 0; j < 4; ++j) {
                    const unsigned* bhp = &bhf[j >> 1][(j & 1) * 2];
                    const unsigned* blp = &blf[j >> 1][(j & 1) * 2];
                    mma_bf16(acc[i][j], ah, bhp);
                    mma_bf16(acc[i][j], ah, blp);
                    mma_bf16(acc[i][j], al, bhp);
                }
            }
        }
    }

    // epilogue: fp32 partial tile (128x64) -> g_part
    const int g = lane >> 2, q = lane & 3;
    const int gb = b * 2 + (isG1 ? 0 : 1);
    float* P = g_part + ((long)((gb * 16 + tile) * KSPLIT + ky)) * (128 * 64);
#pragma unroll
    for (int i = 0; i < 2; ++i)
#pragma unroll
        for (int j = 0; j < 4; ++j) {
            int r0 = mB + i * 16 + g;
            int c  = nB + j * 8 + 2 * q;
            *(float2*)&P[r0 * 64 + c]       = make_float2(acc[i][j][0], acc[i][j][1]);
            *(float2*)&P[(r0 + 8) * 64 + c] = make_float2(acc[i][j][2], acc[i][j][3]);
        }
}

// ---------------------------------------------------------------------------
// Kernel 1b: reduce split-K partials, split fp32 -> hi/lo bf16 factors.
// ---------------------------------------------------------------------------
__global__ void __launch_bounds__(256) reduce_kernel() {
    const int t  = blockIdx.x * 256 + threadIdx.x;
    const int t4 = t << 2;
    const int n    = t4 & 63;
    const int m    = (t4 >> 6) & 127;
    const int tile = (t4 >> 13) & 15;
    const int gb   = t4 >> 17;
    const int b    = gb >> 1;
    const int gemm = gb & 1;

    const float4* P = (const float4*)g_part +
                      ((long)(gb * 16 + tile) * KSPLIT * (128 * 64) + (m * 64 + n)) / 4;
    float4 s = P[0];
#pragma unroll
    for (int k = 1; k < KSPLIT; ++k) {
        float4 v = P[k * (128 * 64 / 4)];
        s.x += v.x; s.y += v.y; s.z += v.z; s.w += v.w;
    }

    unsigned h0, l0, h1, l1;
    split_pair(s.x, s.y, h0, l0);
    split_pair(s.z, s.w, h1, l1);

    const long base = ((long)b * SS + tile * 128 + m) * RR + n;  // SS == HH
    unsigned short* oh = gemm == 0 ? g_Fsh : g_Fhh;
    unsigned short* ol = gemm == 0 ? g_Fsl : g_Fhl;
    *(uint2*)&oh[base] = make_uint2(h0, h1);
    *(uint2*)&ol[base] = make_uint2(l0, l1);
}

// ---------------------------------------------------------------------------
// Kernel 2: Out_b = F_s[b] (S x 64) @ F_h[b]^T (64 x H), fp32 out.
// A resident, 4 h-tiles per CTA, cp.async double-buffered B. (R8-proven form)
// ---------------------------------------------------------------------------
#define OTILES 4
#define OAP 72
#define OBUF (128 * OAP)
#define OBUF_B (OBUF * 2)                // 18432
#define OSM_TOT_BYTES (6 * OBUF_B)       // 110592

__global__ void __launch_bounds__(256, 2) out_kernel(float* __restrict__ Out) {
    extern __shared__ unsigned short sm[];
    const unsigned sbase = (unsigned)__cvta_generic_to_shared(sm);

    const int b = blockIdx.z, s0 = blockIdx.y * 128, hg = blockIdx.x * OTILES;
    const int tid = threadIdx.x;

    auto stageA = [&]() {
        const unsigned short* gh = g_Fsh + ((long)(b * SS + s0)) * RR;
        const unsigned short* gl = g_Fsl + ((long)(b * SS + s0)) * RR;
#pragma unroll
        for (int p = 0; p < 4; ++p) {
            int idx = tid + p * 256;
            int r = idx >> 3, c = (idx & 7) * 8;
            unsigned d = sbase + (unsigned)((r * OAP + c) * 2);
            cp16(d, gh + r * RR + c);
            cp16(d + OBUF_B, gl + r * RR + c);
        }
    };
    auto stageB = [&](int ht, int s) {
        const unsigned short* gh = g_Fhh + ((long)(b * HH + ht * 128)) * RR;
        const unsigned short* gl = g_Fhl + ((long)(b * HH + ht * 128)) * RR;
        const unsigned base = sbase + (unsigned)((2 + 2 * s) * OBUF_B);
#pragma unroll
        for (int p = 0; p < 4; ++p) {
            int idx = tid + p * 256;
            int r = idx >> 3, c = (idx & 7) * 8;
            unsigned d = base + (unsigned)((r * OAP + c) * 2);
            cp16(d, gh + r * RR + c);
            cp16(d + OBUF_B, gl + r * RR + c);
        }
    };

    stageA(); stageB(hg + 0, 0); cp_commit();   // group 0
    stageB(hg + 1, 1); cp_commit();             // group 1

    const int warpId = tid >> 5, lane = tid & 31;
    const int mB = (warpId >> 2) * 64, nB = (warpId & 3) * 32;
    const int g = lane >> 2, q = lane & 3;

    const unsigned aoff = 2 * ((mB + (lane & 15)) * OAP + (lane >> 4) * 8);
    const unsigned aH = sbase + aoff, aL = sbase + OBUF_B + aoff;
    const unsigned boff = 2 * ((nB + (lane & 7) + ((lane & 16) >> 1)) * OAP + (lane & 8));

#pragma unroll 1
    for (int j = 0; j < OTILES; ++j) {
        if (j < OTILES - 1) cp_wait1(); else cp_wait0();
        __syncthreads();

        const unsigned bB = sbase + (unsigned)((2 + 2 * (j & 1)) * OBUF_B);
        const unsigned bH = bB + boff, bL = bB + OBUF_B + boff;

        float acc[4][4][4];
#pragma unroll
        for (int i = 0; i < 4; ++i)
#pragma unroll
            for (int jj = 0; jj < 4; ++jj)
#pragma unroll
                for (int t = 0; t < 4; ++t) acc[i][jj][t] = 0.0f;

#pragma unroll
        for (int kb = 0; kb < 64; kb += 16) {
            unsigned bhf[2][4], blf[2][4];
            ldsm4(bhf[0], bH + kb * 2);
            ldsm4(bhf[1], bH + kb * 2 + 16 * OAP * 2);
            ldsm4(blf[0], bL + kb * 2);
            ldsm4(blf[1], bL + kb * 2 + 16 * OAP * 2);
#pragma unroll
            for (int i = 0; i < 4; ++i) {
                unsigned ah[4], al[4];
                ldsm4(ah, aH + kb * 2 + i * (16 * OAP * 2));
                ldsm4(al, aL + kb * 2 + i * (16 * OAP * 2));
#pragma unroll
                for (int jj = 0; jj < 4; ++jj) {
                    const unsigned* bhp = &bhf[jj >> 1][(jj & 1) * 2];
                    const unsigned* blp = &blf[jj >> 1][(jj & 1) * 2];
                    mma_bf16(acc[i][jj], ah, bhp);
                    mma_bf16(acc[i][jj], ah, blp);
                    mma_bf16(acc[i][jj], al, bhp);
                }
            }
        }

        // store tile j
        float* O = Out + ((long)(b * SS + s0)) * HH + (hg + j) * 128;
#pragma unroll
        for (int i = 0; i < 4; ++i)
#pragma unroll
            for (int jj = 0; jj < 4; ++jj) {
                int r = mB + i * 16 + g;
                int c = nB + jj * 8 + 2 * q;
                *(float2*)&O[(long)r * HH + c]       = make_float2(acc[i][jj][0], acc[i][jj][1]);
                *(float2*)&O[(long)(r + 8) * HH + c] = make_float2(acc[i][jj][2], acc[i][jj][3]);
            }

        if (j + 2 < OTILES) {
            __syncthreads();
            stageB(hg + j + 2, j & 1); cp_commit();
        }
    }
}

// ---------------------------------------------------------------------------
// Launch
// ---------------------------------------------------------------------------
extern "C" void kernel_launch(void* const* d_in, const int* in_sizes, int n_in,
                              void* d_out, int out_size) {
    const float* X    = (const float*)d_in[0];
    const float* Wseq = (const float*)d_in[2];
    const float* Whid = (const float*)d_in[3];
    float* Out = (float*)d_out;

    cudaFuncSetAttribute(fact_kernel, cudaFuncAttributeMaxDynamicSharedMemorySize,
                         FSM_BYTES);
    cudaFuncSetAttribute(out_kernel, cudaFuncAttributeMaxDynamicSharedMemorySize,
                         OSM_TOT_BYTES);

    wsplit_kernel<<<128, 256>>>((const float4*)Wseq, (const float4*)Whid);
    fact_kernel<<<dim3(32, KSPLIT, BB), 256, FSM_BYTES>>>(X);
    reduce_kernel<<<1024, 256>>>();
    out_kernel<<<dim3(HH / 128 / OTILES, SS / 128, BB), 256, OSM_TOT_BYTES>>>(Out);
}

// round 13
// speedup vs baseline: 1.2857x; 1.2857x over previous
#include <cuda_runtime.h>
#include <cuda_bf16.h>

#define BB 4
#define SS 2048
#define HH 2048
#define RR 64
#define KSPLIT 4
#define KPER (2048 / KSPLIT)   // 512 per CTA
#define NC (KPER / 32)         // 16 k-chunks of 32

// ---------------------------------------------------------------------------
// Global scratch (static device arrays; no runtime allocation).
// ---------------------------------------------------------------------------
__device__ __align__(16) unsigned short g_Wsh[RR * SS];
__device__ __align__(16) unsigned short g_Wsl[RR * SS];
__device__ __align__(16) unsigned short g_Whh[RR * HH];
__device__ __align__(16) unsigned short g_Whl[RR * HH];
__device__ __align__(16) unsigned short g_Fsh[BB * SS * RR];  // F_s [b][s][r]
__device__ __align__(16) unsigned short g_Fsl[BB * SS * RR];
__device__ __align__(16) unsigned short g_Fhh[BB * HH * RR];  // F_h [b][h][r]
__device__ __align__(16) unsigned short g_Fhl[BB * HH * RR];
// split-K fp32 partials: [gb(8)][tile(16)][ky(4)][128*64]  (16.8 MB)
__device__ __align__(16) float g_part[8 * 16 * KSPLIT * 128 * 64];

// ---------------------------------------------------------------------------
// Helpers (all volatile — the pinned schedule beats ptxas's unconstrained one
// here (R10), and LDSM volatility is correctness-required across the double
// buffer (R9)).
// ---------------------------------------------------------------------------
__device__ __forceinline__ unsigned pack2(float v0, float v1) {
    __nv_bfloat162 t = __floats2bfloat162_rn(v0, v1);
    return *reinterpret_cast<unsigned*>(&t);
}

__device__ __forceinline__ void split_pair(float v0, float v1, unsigned& h, unsigned& l) {
    h = pack2(v0, v1);
    float h0 = __uint_as_float(h << 16);
    float h1 = __uint_as_float(h & 0xFFFF0000u);
    l = pack2(v0 - h0, v1 - h1);
}

__device__ __forceinline__ void mma_bf16(float c[4], const unsigned a[4], const unsigned b[2]) {
    asm volatile(
        "mma.sync.aligned.m16n8k16.row.col.f32.bf16.bf16.f32 "
        "{%0,%1,%2,%3}, {%4,%5,%6,%7}, {%8,%9}, {%0,%1,%2,%3};\n"
        : "+f"(c[0]), "+f"(c[1]), "+f"(c[2]), "+f"(c[3])
        : "r"(a[0]), "r"(a[1]), "r"(a[2]), "r"(a[3]), "r"(b[0]), "r"(b[1]));
}

__device__ __forceinline__ void ldsm4(unsigned* r, unsigned a) {
    asm volatile("ldmatrix.sync.aligned.m8n8.x4.shared.b16 {%0,%1,%2,%3}, [%4];\n"
                 : "=r"(r[0]), "=r"(r[1]), "=r"(r[2]), "=r"(r[3]) : "r"(a));
}
__device__ __forceinline__ void ldsm4t(unsigned* r, unsigned a) {
    asm volatile("ldmatrix.sync.aligned.m8n8.x4.trans.shared.b16 {%0,%1,%2,%3}, [%4];\n"
                 : "=r"(r[0]), "=r"(r[1]), "=r"(r[2]), "=r"(r[3]) : "r"(a));
}

__device__ __forceinline__ void cp16(unsigned dst, const void* src) {
    asm volatile("cp.async.cg.shared.global [%0], [%1], 16;\n" :: "r"(dst), "l"(src));
}
__device__ __forceinline__ void cp_commit() { asm volatile("cp.async.commit_group;\n"); }
__device__ __forceinline__ void cp_wait1()  { asm volatile("cp.async.wait_group 1;\n" ::: "memory"); }
__device__ __forceinline__ void cp_wait0()  { asm volatile("cp.async.wait_group 0;\n" ::: "memory"); }

// ---------------------------------------------------------------------------
// Kernel 0: split the two small W matrices fp32 -> hi/lo bf16.
// ---------------------------------------------------------------------------
__global__ void __launch_bounds__(256) wsplit_kernel(const float4* __restrict__ Wseq,
                                                     const float4* __restrict__ Whid) {
    const bool second = blockIdx.x >= 64;
    const float4* src = second ? Whid : Wseq;
    uint2* dh = (uint2*)(second ? g_Whh : g_Wsh);
    uint2* dl = (uint2*)(second ? g_Whl : g_Wsl);
    const int n4 = RR * SS / 4;
    for (int i = (blockIdx.x & 63) * 256 + threadIdx.x; i < n4; i += 64 * 256) {
        float4 v = src[i];
        unsigned h0, l0, h1, l1;
        split_pair(v.x, v.y, h0, l0);
        split_pair(v.z, v.w, h1, l1);
        dh[i] = make_uint2(h0, h1);
        dl[i] = make_uint2(l0, l1);
    }
}

// ---------------------------------------------------------------------------
// Kernel 1: fused factor GEMMs, split-K, fused fp32->bf16 split of X.
// minocc 2 (minocc 3 caps regs at 84 -> spills: the R10/R11 regressions).
// ONLY change vs the 86.0us build: inner MMAs in hh/hl/lh j-passes
// (per-accumulator order unchanged -> bitwise identical results).
// ---------------------------------------------------------------------------
#define AP1 40     // G1 A pitch (shorts): [m=128][k=32]
#define AP2 136    // G2 A pitch (shorts): [k=32][m=128]
#define BP  40     // B pitch: [n=64][k=32]
#define ABUF 5120
#define BBUF 2560
#define STG  (2 * ABUF + 2 * BBUF)       // 15360 shorts per stage
#define FSM_BYTES (2 * STG * 2)          // 61440 bytes (2 stages)

__global__ void __launch_bounds__(256, 2) fact_kernel(const float* __restrict__ X) {
    extern __shared__ unsigned short fsm[];
    const unsigned sbase = (unsigned)__cvta_generic_to_shared(fsm);

    const int b = blockIdx.z, ky = blockIdx.y, tid = threadIdx.x;
    const bool isG1 = (blockIdx.x < 16);
    const int tile = isG1 ? blockIdx.x : blockIdx.x - 16;
    const int m0 = tile * 128;
    const int kbase = ky * KPER;

    // ---- A source pointers (fp32 X), 4 x float4 per thread per chunk ----
    const float* pA[4];
    long astep;
    int sr[4], sc[4];
    if (isG1) {
#pragma unroll
        for (int p = 0; p < 4; ++p) {
            int idx = tid + p * 256;
            int row = idx >> 3, c4 = (idx & 7) * 4;
            pA[p] = X + ((long)(b * SS + m0 + row)) * HH + kbase + c4;
            sr[p] = row; sc[p] = c4;
        }
        astep = 32;
    } else {
#pragma unroll
        for (int p = 0; p < 4; ++p) {
            int idx = tid + p * 256;
            int kr = idx >> 5, c4 = (idx & 31) * 4;
            pA[p] = X + ((long)(b * SS + kbase + kr)) * HH + m0 + c4;
            sr[p] = kr; sc[p] = c4;
        }
        astep = (long)32 * HH;
    }
    const int APx = isG1 ? AP1 : AP2;

    // ---- B staging (cp.async) ----
    const unsigned short* Bh_src = isG1 ? g_Whh : g_Wsh;
    const unsigned short* Bl_src = isG1 ? g_Whl : g_Wsl;
    const int brow = tid >> 2, bc = (tid & 3) * 8;
    const long bsoff = (long)brow * (isG1 ? HH : SS) + kbase + bc;
    const unsigned bdst = (unsigned)((2 * ABUF + brow * BP + bc) * 2);

    auto issueB = [&](int kc, int s) {
        const unsigned base = sbase + (unsigned)(s * STG * 2) + bdst;
        const long off = bsoff + kc * 32;
        cp16(base, Bh_src + off);
        cp16(base + BBUF * 2, Bl_src + off);
    };

    float4 pa[4];
#pragma unroll
    for (int p = 0; p < 4; ++p) pa[p] = *(const float4*)pA[p];
    issueB(0, 0); cp_commit();

    const int warpId = tid >> 5, lane = tid & 31;
    const int mB = (warpId >> 1) * 32, nB = (warpId & 1) * 32;

    const unsigned aoff1 = (unsigned)(((mB + (lane & 15)) * AP1 + (lane >> 4) * 8) * 2);
    const unsigned aoff2 = (unsigned)(((((lane & 7) + ((lane & 16) >> 1)) * AP2) +
                                       mB + ((lane >> 3) & 1) * 8) * 2);
    const unsigned boff  = (unsigned)(((nB + (lane & 7) + ((lane & 16) >> 1)) * BP +
                                       (lane & 8)) * 2);

    float acc[2][4][4];
#pragma unroll
    for (int i = 0; i < 2; ++i)
#pragma unroll
        for (int j = 0; j < 4; ++j)
#pragma unroll
            for (int t = 0; t < 4; ++t) acc[i][j][t] = 0.0f;

#pragma unroll 1
    for (int kc = 0; kc < NC; ++kc) {
        const unsigned base = sbase + (unsigned)((kc & 1) * STG * 2);
        const unsigned bAh = base, bAl = base + ABUF * 2;
        const unsigned bBh = base + 2 * ABUF * 2, bBl = bBh + BBUF * 2;

        unsigned short* Ahp = fsm + (kc & 1) * STG;
        unsigned short* Alp = Ahp + ABUF;
#pragma unroll
        for (int p = 0; p < 4; ++p) {
            unsigned h0, l0, h1, l1;
            split_pair(pa[p].x, pa[p].y, h0, l0);
            split_pair(pa[p].z, pa[p].w, h1, l1);
            int o = sr[p] * APx + sc[p];
            *(uint2*)&Ahp[o] = make_uint2(h0, h1);
            *(uint2*)&Alp[o] = make_uint2(l0, l1);
        }
        cp_wait0();
        __syncthreads();

        if (kc + 1 < NC) {
            issueB(kc + 1, (kc + 1) & 1); cp_commit();
#pragma unroll
            for (int p = 0; p < 4; ++p) {
                pA[p] += astep;
                pa[p] = *(const float4*)pA[p];
            }
        }

#pragma unroll
        for (int kb = 0; kb < 32; kb += 16) {
            unsigned bhf[2][4], blf[2][4];
            ldsm4(bhf[0], bBh + boff + kb * 2);
            ldsm4(bhf[1], bBh + boff + kb * 2 + 16 * BP * 2);
            ldsm4(blf[0], bBl + boff + kb * 2);
            ldsm4(blf[1], bBl + boff + kb * 2 + 16 * BP * 2);
#pragma unroll
            for (int i = 0; i < 2; ++i) {
                unsigned ah[4], al[4];
                if (isG1) {
                    unsigned o = aoff1 + (unsigned)(i * 16 * AP1 * 2 + kb * 2);
                    ldsm4(ah, bAh + o);
                    ldsm4(al, bAl + o);
                } else {
                    unsigned o = aoff2 + (unsigned)(kb * AP2 * 2 + i * 16 * 2);
                    ldsm4t(ah, bAh + o);
                    ldsm4t(al, bAl + o);
                }
                // hh / hl / lh passes: per-acc term order unchanged (hh,hl,lh)
                // but dependent MMAs on one acc are now 4 issues apart.
#pragma unroll
                for (int j = 0; j < 4; ++j)
                    mma_bf16(acc[i][j], ah, &bhf[j >> 1][(j & 1) * 2]);
#pragma unroll
                for (int j = 0; j < 4; ++j)
                    mma_bf16(acc[i][j], ah, &blf[j >> 1][(j & 1) * 2]);
#pragma unroll
                for (int j = 0; j < 4; ++j)
                    mma_bf16(acc[i][j], al, &bhf[j >> 1][(j & 1) * 2]);
            }
        }
    }

    // epilogue: fp32 partial tile (128x64) -> g_part
    const int g = lane >> 2, q = lane & 3;
    const int gb = b * 2 + (isG1 ? 0 : 1);
    float* P = g_part + ((long)((gb * 16 + tile) * KSPLIT + ky)) * (128 * 64);
#pragma unroll
    for (int i = 0; i < 2; ++i)
#pragma unroll
        for (int j = 0; j < 4; ++j) {
            int r0 = mB + i * 16 + g;
            int c  = nB + j * 8 + 2 * q;
            *(float2*)&P[r0 * 64 + c]       = make_float2(acc[i][j][0], acc[i][j][1]);
            *(float2*)&P[(r0 + 8) * 64 + c] = make_float2(acc[i][j][2], acc[i][j][3]);
        }
}

// ---------------------------------------------------------------------------
// Kernel 1b: reduce split-K partials, split fp32 -> hi/lo bf16 factors.
// ---------------------------------------------------------------------------
__global__ void __launch_bounds__(256) reduce_kernel() {
    const int t  = blockIdx.x * 256 + threadIdx.x;
    const int t4 = t << 2;
    const int n    = t4 & 63;
    const int m    = (t4 >> 6) & 127;
    const int tile = (t4 >> 13) & 15;
    const int gb   = t4 >> 17;
    const int b    = gb >> 1;
    const int gemm = gb & 1;

    const float4* P = (const float4*)g_part +
                      ((long)(gb * 16 + tile) * KSPLIT * (128 * 64) + (m * 64 + n)) / 4;
    float4 s = P[0];
#pragma unroll
    for (int k = 1; k < KSPLIT; ++k) {
        float4 v = P[k * (128 * 64 / 4)];
        s.x += v.x; s.y += v.y; s.z += v.z; s.w += v.w;
    }

    unsigned h0, l0, h1, l1;
    split_pair(s.x, s.y, h0, l0);
    split_pair(s.z, s.w, h1, l1);

    const long base = ((long)b * SS + tile * 128 + m) * RR + n;  // SS == HH
    unsigned short* oh = gemm == 0 ? g_Fsh : g_Fhh;
    unsigned short* ol = gemm == 0 ? g_Fsl : g_Fhl;
    *(uint2*)&oh[base] = make_uint2(h0, h1);
    *(uint2*)&ol[base] = make_uint2(l0, l1);
}

// ---------------------------------------------------------------------------
// Kernel 2: Out_b = F_s[b] (S x 64) @ F_h[b]^T (64 x H), fp32 out.
// A resident, 4 h-tiles per CTA, cp.async double-buffered B.
// Inner MMAs in hh/hl/lh j-passes (same bitwise per-acc order).
// ---------------------------------------------------------------------------
#define OTILES 4
#define OAP 72
#define OBUF (128 * OAP)
#define OBUF_B (OBUF * 2)                // 18432
#define OSM_TOT_BYTES (6 * OBUF_B)       // 110592

__global__ void __launch_bounds__(256, 2) out_kernel(float* __restrict__ Out) {
    extern __shared__ unsigned short sm[];
    const unsigned sbase = (unsigned)__cvta_generic_to_shared(sm);

    const int b = blockIdx.z, s0 = blockIdx.y * 128, hg = blockIdx.x * OTILES;
    const int tid = threadIdx.x;

    auto stageA = [&]() {
        const unsigned short* gh = g_Fsh + ((long)(b * SS + s0)) * RR;
        const unsigned short* gl = g_Fsl + ((long)(b * SS + s0)) * RR;
#pragma unroll
        for (int p = 0; p < 4; ++p) {
            int idx = tid + p * 256;
            int r = idx >> 3, c = (idx & 7) * 8;
            unsigned d = sbase + (unsigned)((r * OAP + c) * 2);
            cp16(d, gh + r * RR + c);
            cp16(d + OBUF_B, gl + r * RR + c);
        }
    };
    auto stageB = [&](int ht, int s) {
        const unsigned short* gh = g_Fhh + ((long)(b * HH + ht * 128)) * RR;
        const unsigned short* gl = g_Fhl + ((long)(b * HH + ht * 128)) * RR;
        const unsigned base = sbase + (unsigned)((2 + 2 * s) * OBUF_B);
#pragma unroll
        for (int p = 0; p < 4; ++p) {
            int idx = tid + p * 256;
            int r = idx >> 3, c = (idx & 7) * 8;
            unsigned d = base + (unsigned)((r * OAP + c) * 2);
            cp16(d, gh + r * RR + c);
            cp16(d + OBUF_B, gl + r * RR + c);
        }
    };

    stageA(); stageB(hg + 0, 0); cp_commit();   // group 0
    stageB(hg + 1, 1); cp_commit();             // group 1

    const int warpId = tid >> 5, lane = tid & 31;
    const int mB = (warpId >> 2) * 64, nB = (warpId & 3) * 32;
    const int g = lane >> 2, q = lane & 3;

    const unsigned aoff = 2 * ((mB + (lane & 15)) * OAP + (lane >> 4) * 8);
    const unsigned aH = sbase + aoff, aL = sbase + OBUF_B + aoff;
    const unsigned boff = 2 * ((nB + (lane & 7) + ((lane & 16) >> 1)) * OAP + (lane & 8));

#pragma unroll 1
    for (int j = 0; j < OTILES; ++j) {
        if (j < OTILES - 1) cp_wait1(); else cp_wait0();
        __syncthreads();

        const unsigned bB = sbase + (unsigned)((2 + 2 * (j & 1)) * OBUF_B);
        const unsigned bH = bB + boff, bL = bB + OBUF_B + boff;

        float acc[4][4][4];
#pragma unroll
        for (int i = 0; i < 4; ++i)
#pragma unroll
            for (int jj = 0; jj < 4; ++jj)
#pragma unroll
                for (int t = 0; t < 4; ++t) acc[i][jj][t] = 0.0f;

#pragma unroll
        for (int kb = 0; kb < 64; kb += 16) {
            unsigned bhf[2][4], blf[2][4];
            ldsm4(bhf[0], bH + kb * 2);
            ldsm4(bhf[1], bH + kb * 2 + 16 * OAP * 2);
            ldsm4(blf[0], bL + kb * 2);
            ldsm4(blf[1], bL + kb * 2 + 16 * OAP * 2);
#pragma unroll
            for (int i = 0; i < 4; ++i) {
                unsigned ah[4], al[4];
                ldsm4(ah, aH + kb * 2 + i * (16 * OAP * 2));
                ldsm4(al, aL + kb * 2 + i * (16 * OAP * 2));
                // hh / hl / lh passes (per-acc order unchanged)
#pragma unroll
                for (int jj = 0; jj < 4; ++jj)
                    mma_bf16(acc[i][jj], ah, &bhf[jj >> 1][(jj & 1) * 2]);
#pragma unroll
                for (int jj = 0; jj < 4; ++jj)
                    mma_bf16(acc[i][jj], ah, &blf[jj >> 1][(jj & 1) * 2]);
#pragma unroll
                for (int jj = 0; jj < 4; ++jj)
                    mma_bf16(acc[i][jj], al, &bhf[jj >> 1][(jj & 1) * 2]);
            }
        }

        // store tile j
        float* O = Out + ((long)(b * SS + s0)) * HH + (hg + j) * 128;
#pragma unroll
        for (int i = 0; i < 4; ++i)
#pragma unroll
            for (int jj = 0; jj < 4; ++jj) {
                int r = mB + i * 16 + g;
                int c = nB + jj * 8 + 2 * q;
                *(float2*)&O[(long)r * HH + c]       = make_float2(acc[i][jj][0], acc[i][jj][1]);
                *(float2*)&O[(long)(r + 8) * HH + c] = make_float2(acc[i][jj][2], acc[i][jj][3]);
            }

        if (j + 2 < OTILES) {
            __syncthreads();
            stageB(hg + j + 2, j & 1); cp_commit();
        }
    }
}

// ---------------------------------------------------------------------------
// Launch
// ---------------------------------------------------------------------------
extern "C" void kernel_launch(void* const* d_in, const int* in_sizes, int n_in,
                              void* d_out, int out_size) {
    const float* X    = (const float*)d_in[0];
    const float* Wseq = (const float*)d_in[2];
    const float* Whid = (const float*)d_in[3];
    float* Out = (float*)d_out;

    cudaFuncSetAttribute(fact_kernel, cudaFuncAttributeMaxDynamicSharedMemorySize,
                         FSM_BYTES);
    cudaFuncSetAttribute(out_kernel, cudaFuncAttributeMaxDynamicSharedMemorySize,
                         OSM_TOT_BYTES);

    wsplit_kernel<<<128, 256>>>((const float4*)Wseq, (const float4*)Whid);
    fact_kernel<<<dim3(32, KSPLIT, BB), 256, FSM_BYTES>>>(X);
    reduce_kernel<<<1024, 256>>>();
    out_kernel<<<dim3(HH / 128 / OTILES, SS / 128, BB), 256, OSM_TOT_BYTES>>>(Out);
}

// round 15
// speedup vs baseline: 1.4974x; 1.1646x over previous
#include <cuda_runtime.h>
#include <cuda_bf16.h>
#include <cuda_fp16.h>

#define BB 4
#define SS 2048
#define HH 2048
#define RR 64
#define KSPLIT 4
#define KPER (2048 / KSPLIT)   // 512 per CTA
#define NC (KPER / 32)         // 16 k-chunks of 32

// ---------------------------------------------------------------------------
// Global scratch (static device arrays; no runtime allocation).
// W and F_h: fp16 hi/lo split (exact-ish). F_s: single fp16.
// ---------------------------------------------------------------------------
__device__ __align__(16) unsigned short g_Wsh[RR * SS];
__device__ __align__(16) unsigned short g_Wsl[RR * SS];
__device__ __align__(16) unsigned short g_Whh[RR * HH];
__device__ __align__(16) unsigned short g_Whl[RR * HH];
__device__ __align__(16) unsigned short g_Fsh[BB * SS * RR];  // F_s single fp16 [b][s][r]
__device__ __align__(16) unsigned short g_Fhh[BB * HH * RR];  // F_h hi [b][h][r]
__device__ __align__(16) unsigned short g_Fhl[BB * HH * RR];  // F_h lo
// split-K fp32 partials: [gb(8)][tile(16)][ky(4)][128*64]  (16.8 MB)
__device__ __align__(16) float g_part[8 * 16 * KSPLIT * 128 * 64];

// ---------------------------------------------------------------------------
// Helpers (volatile forms: pinned schedule proven best R10-R12; LDSM
// volatility correctness-required across double buffers R9).
// ---------------------------------------------------------------------------
__device__ __forceinline__ unsigned packh2(float v0, float v1) {
    __half2 t = __floats2half2_rn(v0, v1);
    return *reinterpret_cast<unsigned*>(&t);
}

// fp16 two-term split of a float pair
__device__ __forceinline__ void split_pair_h(float v0, float v1, unsigned& h, unsigned& l) {
    h = packh2(v0, v1);
    __half2 th = *reinterpret_cast<__half2*>(&h);
    float h0 = __half2float(__low2half(th));
    float h1 = __half2float(__high2half(th));
    l = packh2(v0 - h0, v1 - h1);
}

__device__ __forceinline__ void mma_fp16(float c[4], const unsigned a[4], const unsigned b[2]) {
    asm volatile(
        "mma.sync.aligned.m16n8k16.row.col.f32.f16.f16.f32 "
        "{%0,%1,%2,%3}, {%4,%5,%6,%7}, {%8,%9}, {%0,%1,%2,%3};\n"
        : "+f"(c[0]), "+f"(c[1]), "+f"(c[2]), "+f"(c[3])
        : "r"(a[0]), "r"(a[1]), "r"(a[2]), "r"(a[3]), "r"(b[0]), "r"(b[1]));
}

__device__ __forceinline__ void ldsm4(unsigned* r, unsigned a) {
    asm volatile("ldmatrix.sync.aligned.m8n8.x4.shared.b16 {%0,%1,%2,%3}, [%4];\n"
                 : "=r"(r[0]), "=r"(r[1]), "=r"(r[2]), "=r"(r[3]) : "r"(a));
}
__device__ __forceinline__ void ldsm4t(unsigned* r, unsigned a) {
    asm volatile("ldmatrix.sync.aligned.m8n8.x4.trans.shared.b16 {%0,%1,%2,%3}, [%4];\n"
                 : "=r"(r[0]), "=r"(r[1]), "=r"(r[2]), "=r"(r[3]) : "r"(a));
}

__device__ __forceinline__ void cp16(unsigned dst, const void* src) {
    asm volatile("cp.async.cg.shared.global [%0], [%1], 16;\n" :: "r"(dst), "l"(src));
}
__device__ __forceinline__ void cp_commit() { asm volatile("cp.async.commit_group;\n"); }
__device__ __forceinline__ void cp_wait1()  { asm volatile("cp.async.wait_group 1;\n" ::: "memory"); }
__device__ __forceinline__ void cp_wait0()  { asm volatile("cp.async.wait_group 0;\n" ::: "memory"); }

// ---------------------------------------------------------------------------
// Kernel 0: split the two small W matrices fp32 -> fp16 hi/lo.
// ---------------------------------------------------------------------------
__global__ void __launch_bounds__(256) wsplit_kernel(const float4* __restrict__ Wseq,
                                                     const float4* __restrict__ Whid) {
    const bool second = blockIdx.x >= 64;
    const float4* src = second ? Whid : Wseq;
    uint2* dh = (uint2*)(second ? g_Whh : g_Wsh);
    uint2* dl = (uint2*)(second ? g_Whl : g_Wsl);
    const int n4 = RR * SS / 4;
    for (int i = (blockIdx.x & 63) * 256 + threadIdx.x; i < n4; i += 64 * 256) {
        float4 v = src[i];
        unsigned h0, l0, h1, l1;
        split_pair_h(v.x, v.y, h0, l0);
        split_pair_h(v.z, v.w, h1, l1);
        dh[i] = make_uint2(h0, h1);
        dl[i] = make_uint2(l0, l1);
    }
}

// ---------------------------------------------------------------------------
// Kernel 1: fused factor GEMMs, split-K, fp16 2-MMA scheme.
//   A = X (SINGLE fp16, converted in-register from fp32)
//   B = W (fp16 hi/lo split, pre-split, cp.async)
//   acc += a*bh + a*bl  (error = X fp16 rounding ~2e-4, within budget)
//   G1 (x<16):  F_s rows = X[m][k] (ldsm) @ Whid^T
//   G2 (x>=16): F_h rows = X^T as A=[k][m] (ldsm.trans) @ Wseq^T
// ---------------------------------------------------------------------------
#define AP1 40     // G1 A pitch (shorts): [m=128][k=32]
#define AP2 136    // G2 A pitch (shorts): [k=32][m=128]
#define BP  40     // B pitch: [n=64][k=32]
#define ABUF 5120                        // shorts: A single buffer
#define BBUF 2560                        // shorts per B sub-buffer
#define STG  (ABUF + 2 * BBUF)           // 10240 shorts per stage
#define FSM_BYTES (2 * STG * 2)          // 40960 bytes (2 stages)

__global__ void __launch_bounds__(256, 2) fact_kernel(const float* __restrict__ X) {
    extern __shared__ unsigned short fsm[];
    const unsigned sbase = (unsigned)__cvta_generic_to_shared(fsm);

    const int b = blockIdx.z, ky = blockIdx.y, tid = threadIdx.x;
    const bool isG1 = (blockIdx.x < 16);
    const int tile = isG1 ? blockIdx.x : blockIdx.x - 16;
    const int m0 = tile * 128;
    const int kbase = ky * KPER;

    // ---- A source pointers (fp32 X), 4 x float4 per thread per chunk ----
    const float* pA[4];
    long astep;
    int sr[4], sc[4];
    if (isG1) {
#pragma unroll
        for (int p = 0; p < 4; ++p) {
            int idx = tid + p * 256;
            int row = idx >> 3, c4 = (idx & 7) * 4;
            pA[p] = X + ((long)(b * SS + m0 + row)) * HH + kbase + c4;
            sr[p] = row; sc[p] = c4;
        }
        astep = 32;
    } else {
#pragma unroll
        for (int p = 0; p < 4; ++p) {
            int idx = tid + p * 256;
            int kr = idx >> 5, c4 = (idx & 31) * 4;
            pA[p] = X + ((long)(b * SS + kbase + kr)) * HH + m0 + c4;
            sr[p] = kr; sc[p] = c4;
        }
        astep = (long)32 * HH;
    }
    const int APx = isG1 ? AP1 : AP2;

    // ---- B staging (cp.async): 64 n-rows x 32 k, hi+lo fp16 ----
    const unsigned short* Bh_src = isG1 ? g_Whh : g_Wsh;
    const unsigned short* Bl_src = isG1 ? g_Whl : g_Wsl;
    const int brow = tid >> 2, bc = (tid & 3) * 8;
    const long bsoff = (long)brow * (isG1 ? HH : SS) + kbase + bc;
    const unsigned bdst = (unsigned)((ABUF + brow * BP + bc) * 2);

    auto issueB = [&](int kc, int s) {
        const unsigned base = sbase + (unsigned)(s * STG * 2) + bdst;
        const long off = bsoff + kc * 32;
        cp16(base, Bh_src + off);
        cp16(base + BBUF * 2, Bl_src + off);
    };

    float4 pa[4];
#pragma unroll
    for (int p = 0; p < 4; ++p) pa[p] = *(const float4*)pA[p];
    issueB(0, 0); cp_commit();

    const int wid = tid >> 5, lane = tid & 31;
    const int mB = (wid >> 1) * 32, nB = (wid & 1) * 32;

    const unsigned aoff1 = (unsigned)(((mB + (lane & 15)) * AP1 + (lane >> 4) * 8) * 2);
    const unsigned aoff2 = (unsigned)(((((lane & 7) + ((lane & 16) >> 1)) * AP2) +
                                       mB + ((lane >> 3) & 1) * 8) * 2);
    const unsigned boff  = (unsigned)(((nB + (lane & 7) + ((lane & 16) >> 1)) * BP +
                                       (lane & 8)) * 2);

    float acc[2][4][4];
#pragma unroll
    for (int i = 0; i < 2; ++i)
#pragma unroll
        for (int j = 0; j < 4; ++j)
#pragma unroll
            for (int t = 0; t < 4; ++t) acc[i][j][t] = 0.0f;

#pragma unroll 1
    for (int kc = 0; kc < NC; ++kc) {
        const unsigned base = sbase + (unsigned)((kc & 1) * STG * 2);
        const unsigned bA  = base;
        const unsigned bBh = base + ABUF * 2, bBl = bBh + BBUF * 2;

        // convert prefetched fp32 A regs -> single fp16 smem
        unsigned short* Ap = fsm + (kc & 1) * STG;
#pragma unroll
        for (int p = 0; p < 4; ++p) {
            int o = sr[p] * APx + sc[p];
            *(uint2*)&Ap[o] = make_uint2(packh2(pa[p].x, pa[p].y),
                                         packh2(pa[p].z, pa[p].w));
        }
        cp_wait0();
        __syncthreads();

        if (kc + 1 < NC) {
            issueB(kc + 1, (kc + 1) & 1); cp_commit();
#pragma unroll
            for (int p = 0; p < 4; ++p) {
                pA[p] += astep;
                pa[p] = *(const float4*)pA[p];
            }
        }

#pragma unroll
        for (int kb = 0; kb < 32; kb += 16) {
            unsigned bhf[2][4], blf[2][4];
            ldsm4(bhf[0], bBh + boff + kb * 2);
            ldsm4(bhf[1], bBh + boff + kb * 2 + 16 * BP * 2);
            ldsm4(blf[0], bBl + boff + kb * 2);
            ldsm4(blf[1], bBl + boff + kb * 2 + 16 * BP * 2);
#pragma unroll
            for (int i = 0; i < 2; ++i) {
                unsigned a[4];
                if (isG1) {
                    ldsm4(a, bA + aoff1 + (unsigned)(i * 16 * AP1 * 2 + kb * 2));
                } else {
                    ldsm4t(a, bA + aoff2 + (unsigned)(kb * AP2 * 2 + i * 16 * 2));
                }
#pragma unroll
                for (int j = 0; j < 4; ++j)
                    mma_fp16(acc[i][j], a, &bhf[j >> 1][(j & 1) * 2]);
#pragma unroll
                for (int j = 0; j < 4; ++j)
                    mma_fp16(acc[i][j], a, &blf[j >> 1][(j & 1) * 2]);
            }
        }
    }

    // epilogue: fp32 partial tile (128x64) -> g_part
    const int g = lane >> 2, q = lane & 3;
    const int gb = b * 2 + (isG1 ? 0 : 1);
    float* P = g_part + ((long)((gb * 16 + tile) * KSPLIT + ky)) * (128 * 64);
#pragma unroll
    for (int i = 0; i < 2; ++i)
#pragma unroll
        for (int j = 0; j < 4; ++j) {
            int r0 = mB + i * 16 + g;
            int c  = nB + j * 8 + 2 * q;
            *(float2*)&P[r0 * 64 + c]       = make_float2(acc[i][j][0], acc[i][j][1]);
            *(float2*)&P[(r0 + 8) * 64 + c] = make_float2(acc[i][j][2], acc[i][j][3]);
        }
}

// ---------------------------------------------------------------------------
// Kernel 1b: reduce split-K partials.
//   F_s -> single fp16. F_h -> fp16 hi/lo split.
// ---------------------------------------------------------------------------
__global__ void __launch_bounds__(256) reduce_kernel() {
    const int t  = blockIdx.x * 256 + threadIdx.x;
    const int t4 = t << 2;
    const int n    = t4 & 63;
    const int m    = (t4 >> 6) & 127;
    const int tile = (t4 >> 13) & 15;
    const int gb   = t4 >> 17;
    const int b    = gb >> 1;
    const int gemm = gb & 1;

    const float4* P = (const float4*)g_part +
                      ((long)(gb * 16 + tile) * KSPLIT * (128 * 64) + (m * 64 + n)) / 4;
    float4 s = P[0];
#pragma unroll
    for (int k = 1; k < KSPLIT; ++k) {
        float4 v = P[k * (128 * 64 / 4)];
        s.x += v.x; s.y += v.y; s.z += v.z; s.w += v.w;
    }

    const long base = ((long)b * SS + tile * 128 + m) * RR + n;  // SS == HH
    if (gemm == 0) {
        *(uint2*)&g_Fsh[base] = make_uint2(packh2(s.x, s.y), packh2(s.z, s.w));
    } else {
        unsigned h0, l0, h1, l1;
        split_pair_h(s.x, s.y, h0, l0);
        split_pair_h(s.z, s.w, h1, l1);
        *(uint2*)&g_Fhh[base] = make_uint2(h0, h1);
        *(uint2*)&g_Fhl[base] = make_uint2(l0, l1);
    }
}

// ---------------------------------------------------------------------------
// Kernel 2: Out_b = F_s[b] (S x 64) @ F_h[b]^T (64 x H), fp32 out.
// A = F_s single fp16 resident; B = F_h hi/lo fp16, double-buffered cp.async.
// 2 MMAs per product: a*bh + a*bl.
// ---------------------------------------------------------------------------
#define OTILES 4
#define OAP 72
#define OBUF (128 * OAP)
#define OBUF_B (OBUF * 2)                // 18432 bytes per buffer
#define OSM_TOT_BYTES (5 * OBUF_B)       // A + 2 stages x (Bh,Bl) = 92160

__global__ void __launch_bounds__(256, 2) out_kernel(float* __restrict__ Out) {
    extern __shared__ unsigned short sm[];
    const unsigned sbase = (unsigned)__cvta_generic_to_shared(sm);

    const int b = blockIdx.z, s0 = blockIdx.y * 128, hg = blockIdx.x * OTILES;
    const int tid = threadIdx.x;

    auto stageA = [&]() {
        const unsigned short* gh = g_Fsh + ((long)(b * SS + s0)) * RR;
#pragma unroll
        for (int p = 0; p < 4; ++p) {
            int idx = tid + p * 256;
            int r = idx >> 3, c = (idx & 7) * 8;
            cp16(sbase + (unsigned)((r * OAP + c) * 2), gh + r * RR + c);
        }
    };
    auto stageB = [&](int ht, int s) {
        const unsigned short* gh = g_Fhh + ((long)(b * HH + ht * 128)) * RR;
        const unsigned short* gl = g_Fhl + ((long)(b * HH + ht * 128)) * RR;
        const unsigned base = sbase + (unsigned)((1 + 2 * s) * OBUF_B);
#pragma unroll
        for (int p = 0; p < 4; ++p) {
            int idx = tid + p * 256;
            int r = idx >> 3, c = (idx & 7) * 8;
            unsigned d = base + (unsigned)((r * OAP + c) * 2);
            cp16(d, gh + r * RR + c);
            cp16(d + OBUF_B, gl + r * RR + c);
        }
    };

    stageA(); stageB(hg + 0, 0); cp_commit();   // group 0
    stageB(hg + 1, 1); cp_commit();             // group 1

    const int warpId = tid >> 5, lane = tid & 31;
    const int mB = (warpId >> 2) * 64, nB = (warpId & 3) * 32;
    const int g = lane >> 2, q = lane & 3;

    const unsigned aoff = 2 * ((mB + (lane & 15)) * OAP + (lane >> 4) * 8);
    const unsigned aA = sbase + aoff;
    const unsigned boff = 2 * ((nB + (lane & 7) + ((lane & 16) >> 1)) * OAP + (lane & 8));

#pragma unroll 1
    for (int j = 0; j < OTILES; ++j) {
        if (j < OTILES - 1) cp_wait1(); else cp_wait0();
        __syncthreads();

        const unsigned bB = sbase + (unsigned)((1 + 2 * (j & 1)) * OBUF_B);
        const unsigned bH = bB + boff, bL = bB + OBUF_B + boff;

        float acc[4][4][4];
#pragma unroll
        for (int i = 0; i < 4; ++i)
#pragma unroll
            for (int jj = 0; jj < 4; ++jj)
#pragma unroll
                for (int t = 0; t < 4; ++t) acc[i][jj][t] = 0.0f;

#pragma unroll
        for (int kb = 0; kb < 64; kb += 16) {
            unsigned bhf[2][4], blf[2][4];
            ldsm4(bhf[0], bH + kb * 2);
            ldsm4(bhf[1], bH + kb * 2 + 16 * OAP * 2);
            ldsm4(blf[0], bL + kb * 2);
            ldsm4(blf[1], bL + kb * 2 + 16 * OAP * 2);
#pragma unroll
            for (int i = 0; i < 4; ++i) {
                unsigned a[4];
                ldsm4(a, aA + kb * 2 + i * (16 * OAP * 2));
#pragma unroll
                for (int jj = 0; jj < 4; ++jj)
                    mma_fp16(acc[i][jj], a, &bhf[jj >> 1][(jj & 1) * 2]);
#pragma unroll
                for (int jj = 0; jj < 4; ++jj)
                    mma_fp16(acc[i][jj], a, &blf[jj >> 1][(jj & 1) * 2]);
            }
        }

        // store tile j
        float* O = Out + ((long)(b * SS + s0)) * HH + (hg + j) * 128;
#pragma unroll
        for (int i = 0; i < 4; ++i)
#pragma unroll
            for (int jj = 0; jj < 4; ++jj) {
                int r = mB + i * 16 + g;
                int c = nB + jj * 8 + 2 * q;
                *(float2*)&O[(long)r * HH + c]       = make_float2(acc[i][jj][0], acc[i][jj][1]);
                *(float2*)&O[(long)(r + 8) * HH + c] = make_float2(acc[i][jj][2], acc[i][jj][3]);
            }

        if (j + 2 < OTILES) {
            __syncthreads();
            stageB(hg + j + 2, j & 1); cp_commit();
        }
    }
}

// ---------------------------------------------------------------------------
// Launch
// ---------------------------------------------------------------------------
extern "C" void kernel_launch(void* const* d_in, const int* in_sizes, int n_in,
                              void* d_out, int out_size) {
    const float* X    = (const float*)d_in[0];
    const float* Wseq = (const float*)d_in[2];
    const float* Whid = (const float*)d_in[3];
    float* Out = (float*)d_out;

    cudaFuncSetAttribute(fact_kernel, cudaFuncAttributeMaxDynamicSharedMemorySize,
                         FSM_BYTES);
    cudaFuncSetAttribute(out_kernel, cudaFuncAttributeMaxDynamicSharedMemorySize,
                         OSM_TOT_BYTES);

    wsplit_kernel<<<128, 256>>>((const float4*)Wseq, (const float4*)Whid);
    fact_kernel<<<dim3(32, KSPLIT, BB), 256, FSM_BYTES>>>(X);
    reduce_kernel<<<1024, 256>>>();
    out_kernel<<<dim3(HH / 128 / OTILES, SS / 128, BB), 256, OSM_TOT_BYTES>>>(Out);
}

// round 16
// speedup vs baseline: 1.6271x; 1.0866x over previous
#include <cuda_runtime.h>
#include <cuda_fp16.h>

#define BB 4
#define SS 2048
#define HH 2048
#define RR 64
#define KSPLIT 4
#define KPER (2048 / KSPLIT)   // 512 per CTA
#define NC (KPER / 32)         // 16 k-chunks of 32

// ---------------------------------------------------------------------------
// Global scratch (static device arrays; no runtime allocation).
// All operands single fp16 (1 MMA per product; calibrated err ~5e-4 < 1e-3).
// ---------------------------------------------------------------------------
__device__ __align__(16) unsigned short g_Ws[RR * SS];        // Wseq fp16
__device__ __align__(16) unsigned short g_Wh[RR * HH];        // Whid fp16
__device__ __align__(16) unsigned short g_Fs[BB * SS * RR];   // F_s fp16 [b][s][r]
__device__ __align__(16) unsigned short g_Fh[BB * HH * RR];   // F_h fp16 [b][h][r]
// split-K fp32 partials: [gb(8)][tile(16)][ky(4)][128*64]  (16.8 MB)
__device__ __align__(16) float g_part[8 * 16 * KSPLIT * 128 * 64];
__device__ int g_cnt[128];   // split-K tickets (zero-init; self-resetting)

// ---------------------------------------------------------------------------
// Helpers (volatile forms: pinned schedule proven best R10-R12; LDSM
// volatility correctness-required across double buffers R9).
// ---------------------------------------------------------------------------
__device__ __forceinline__ unsigned packh2(float v0, float v1) {
    __half2 t = __floats2half2_rn(v0, v1);
    return *reinterpret_cast<unsigned*>(&t);
}

__device__ __forceinline__ void mma_fp16(float c[4], const unsigned a[4], const unsigned b[2]) {
    asm volatile(
        "mma.sync.aligned.m16n8k16.row.col.f32.f16.f16.f32 "
        "{%0,%1,%2,%3}, {%4,%5,%6,%7}, {%8,%9}, {%0,%1,%2,%3};\n"
        : "+f"(c[0]), "+f"(c[1]), "+f"(c[2]), "+f"(c[3])
        : "r"(a[0]), "r"(a[1]), "r"(a[2]), "r"(a[3]), "r"(b[0]), "r"(b[1]));
}

__device__ __forceinline__ void ldsm4(unsigned* r, unsigned a) {
    asm volatile("ldmatrix.sync.aligned.m8n8.x4.shared.b16 {%0,%1,%2,%3}, [%4];\n"
                 : "=r"(r[0]), "=r"(r[1]), "=r"(r[2]), "=r"(r[3]) : "r"(a));
}
__device__ __forceinline__ void ldsm4t(unsigned* r, unsigned a) {
    asm volatile("ldmatrix.sync.aligned.m8n8.x4.trans.shared.b16 {%0,%1,%2,%3}, [%4];\n"
                 : "=r"(r[0]), "=r"(r[1]), "=r"(r[2]), "=r"(r[3]) : "r"(a));
}

__device__ __forceinline__ void cp16(unsigned dst, const void* src) {
    asm volatile("cp.async.cg.shared.global [%0], [%1], 16;\n" :: "r"(dst), "l"(src));
}
__device__ __forceinline__ void cp_commit() { asm volatile("cp.async.commit_group;\n"); }
__device__ __forceinline__ void cp_wait1()  { asm volatile("cp.async.wait_group 1;\n" ::: "memory"); }
__device__ __forceinline__ void cp_wait0()  { asm volatile("cp.async.wait_group 0;\n" ::: "memory"); }

// ---------------------------------------------------------------------------
// Kernel 0: convert the two small W matrices fp32 -> single fp16.
// ---------------------------------------------------------------------------
__global__ void __launch_bounds__(256) wsplit_kernel(const float4* __restrict__ Wseq,
                                                     const float4* __restrict__ Whid) {
    const bool second = blockIdx.x >= 64;
    const float4* src = second ? Whid : Wseq;
    uint2* dh = (uint2*)(second ? g_Wh : g_Ws);
    const int n4 = RR * SS / 4;
    for (int i = (blockIdx.x & 63) * 256 + threadIdx.x; i < n4; i += 64 * 256) {
        float4 v = src[i];
        dh[i] = make_uint2(packh2(v.x, v.y), packh2(v.z, v.w));
    }
}

// ---------------------------------------------------------------------------
// Kernel 1: fused factor GEMMs, split-K, single-fp16 1-MMA scheme, with
// the split-K reduction fused in (last-CTA-reduces ticket pattern).
//   G1 (x<16):  F_s rows = X[m][k] (ldsm) @ Whid^T
//   G2 (x>=16): F_h rows = X^T as A=[k][m] (ldsm.trans) @ Wseq^T
// ---------------------------------------------------------------------------
#define AP1 40     // G1 A pitch (shorts): [m=128][k=32]
#define AP2 136    // G2 A pitch (shorts): [k=32][m=128]
#define BP  40     // B pitch: [n=64][k=32]
#define ABUF 5120                        // shorts: A buffer
#define BBUF 2560                        // shorts: B buffer
#define STG  (ABUF + BBUF)               // 7680 shorts per stage
#define FSM_BYTES (2 * STG * 2)          // 30720 bytes (2 stages)

__global__ void __launch_bounds__(256, 2) fact_kernel(const float* __restrict__ X) {
    extern __shared__ unsigned short fsm[];
    __shared__ int s_old;
    const unsigned sbase = (unsigned)__cvta_generic_to_shared(fsm);

    const int b = blockIdx.z, ky = blockIdx.y, tid = threadIdx.x;
    const bool isG1 = (blockIdx.x < 16);
    const int tile = isG1 ? blockIdx.x : blockIdx.x - 16;
    const int m0 = tile * 128;
    const int kbase = ky * KPER;

    // ---- A source pointers (fp32 X), 4 x float4 per thread per chunk ----
    const float* pA[4];
    long astep;
    int sr[4], sc[4];
    if (isG1) {
#pragma unroll
        for (int p = 0; p < 4; ++p) {
            int idx = tid + p * 256;
            int row = idx >> 3, c4 = (idx & 7) * 4;
            pA[p] = X + ((long)(b * SS + m0 + row)) * HH + kbase + c4;
            sr[p] = row; sc[p] = c4;
        }
        astep = 32;
    } else {
#pragma unroll
        for (int p = 0; p < 4; ++p) {
            int idx = tid + p * 256;
            int kr = idx >> 5, c4 = (idx & 31) * 4;
            pA[p] = X + ((long)(b * SS + kbase + kr)) * HH + m0 + c4;
            sr[p] = kr; sc[p] = c4;
        }
        astep = (long)32 * HH;
    }
    const int APx = isG1 ? AP1 : AP2;

    // ---- B staging (cp.async): 64 n-rows x 32 k fp16, one cp16/thread ----
    const unsigned short* B_src = isG1 ? g_Wh : g_Ws;
    const int brow = tid >> 2, bc = (tid & 3) * 8;
    const long bsoff = (long)brow * (isG1 ? HH : SS) + kbase + bc;
    const unsigned bdst = (unsigned)((ABUF + brow * BP + bc) * 2);

    auto issueB = [&](int kc, int s) {
        cp16(sbase + (unsigned)(s * STG * 2) + bdst, B_src + bsoff + kc * 32);
    };

    float4 pa[4];
#pragma unroll
    for (int p = 0; p < 4; ++p) pa[p] = *(const float4*)pA[p];
    issueB(0, 0); cp_commit();

    const int wid = tid >> 5, lane = tid & 31;
    const int mB = (wid >> 1) * 32, nB = (wid & 1) * 32;

    const unsigned aoff1 = (unsigned)(((mB + (lane & 15)) * AP1 + (lane >> 4) * 8) * 2);
    const unsigned aoff2 = (unsigned)(((((lane & 7) + ((lane & 16) >> 1)) * AP2) +
                                       mB + ((lane >> 3) & 1) * 8) * 2);
    const unsigned boff  = (unsigned)(((nB + (lane & 7) + ((lane & 16) >> 1)) * BP +
                                       (lane & 8)) * 2);

    float acc[2][4][4];
#pragma unroll
    for (int i = 0; i < 2; ++i)
#pragma unroll
        for (int j = 0; j < 4; ++j)
#pragma unroll
            for (int t = 0; t < 4; ++t) acc[i][j][t] = 0.0f;

#pragma unroll 1
    for (int kc = 0; kc < NC; ++kc) {
        const unsigned base = sbase + (unsigned)((kc & 1) * STG * 2);
        const unsigned bA = base, bB = base + ABUF * 2;

        // convert prefetched fp32 A regs -> fp16 smem
        unsigned short* Ap = fsm + (kc & 1) * STG;
#pragma unroll
        for (int p = 0; p < 4; ++p) {
            int o = sr[p] * APx + sc[p];
            *(uint2*)&Ap[o] = make_uint2(packh2(pa[p].x, pa[p].y),
                                         packh2(pa[p].z, pa[p].w));
        }
        cp_wait0();
        __syncthreads();

        if (kc + 1 < NC) {
            issueB(kc + 1, (kc + 1) & 1); cp_commit();
#pragma unroll
            for (int p = 0; p < 4; ++p) {
                pA[p] += astep;
                pa[p] = *(const float4*)pA[p];
            }
        }

#pragma unroll
        for (int kb = 0; kb < 32; kb += 16) {
            unsigned bhf[2][4];
            ldsm4(bhf[0], bB + boff + kb * 2);
            ldsm4(bhf[1], bB + boff + kb * 2 + 16 * BP * 2);
#pragma unroll
            for (int i = 0; i < 2; ++i) {
                unsigned a[4];
                if (isG1) {
                    ldsm4(a, bA + aoff1 + (unsigned)(i * 16 * AP1 * 2 + kb * 2));
                } else {
                    ldsm4t(a, bA + aoff2 + (unsigned)(kb * AP2 * 2 + i * 16 * 2));
                }
#pragma unroll
                for (int j = 0; j < 4; ++j)
                    mma_fp16(acc[i][j], a, &bhf[j >> 1][(j & 1) * 2]);
            }
        }
    }

    // ---- epilogue: partial write + fused serial split-K reduction ----
    const int g = lane >> 2, q = lane & 3;
    const int gb = b * 2 + (isG1 ? 0 : 1);
    const int slot = gb * 16 + tile;
    float* P = g_part + ((long)slot * KSPLIT + ky) * (128 * 64);
#pragma unroll
    for (int i = 0; i < 2; ++i)
#pragma unroll
        for (int j = 0; j < 4; ++j) {
            int r0 = mB + i * 16 + g;
            int c  = nB + j * 8 + 2 * q;
            *(float2*)&P[r0 * 64 + c]       = make_float2(acc[i][j][0], acc[i][j][1]);
            *(float2*)&P[(r0 + 8) * 64 + c] = make_float2(acc[i][j][2], acc[i][j][3]);
        }

    __threadfence();           // release this CTA's partial
    __syncthreads();           // all threads' fences done before the ticket
    if (tid == 0) s_old = atomicAdd(&g_cnt[slot], 1);
    __syncthreads();

    if (s_old == KSPLIT - 1) { // last arriver reduces this tile
        __threadfence();       // acquire other CTAs' partials
        const float4* Pb = (const float4*)(g_part + (long)slot * KSPLIT * (128 * 64));
        unsigned short* F = isG1 ? g_Fs : g_Fh;
#pragma unroll
        for (int p = 0; p < 8; ++p) {
            int idx = tid + p * 256;          // 0..2047 float4s
            float4 s = Pb[idx];
#pragma unroll
            for (int k = 1; k < KSPLIT; ++k) {
                float4 v = Pb[idx + k * 2048];
                s.x += v.x; s.y += v.y; s.z += v.z; s.w += v.w;
            }
            int e = idx << 2;
            int m = e >> 6, n = e & 63;
            long basef = ((long)b * SS + tile * 128 + m) * RR + n;  // SS == HH
            *(uint2*)&F[basef] = make_uint2(packh2(s.x, s.y), packh2(s.z, s.w));
        }
        if (tid == 0) g_cnt[slot] = 0;   // self-reset for next launch
    }
}

// ---------------------------------------------------------------------------
// Kernel 2: Out_b = F_s[b] (S x 64) @ F_h[b]^T (64 x H), fp32 out.
// A = F_s fp16 resident; B = F_h fp16, double-buffered cp.async. 1 MMA/product.
// ---------------------------------------------------------------------------
#define OTILES 4
#define OAP 72
#define OBUF (128 * OAP)
#define OBUF_B (OBUF * 2)                // 18432 bytes per buffer
#define OSM_TOT_BYTES (3 * OBUF_B)       // A + 2 B stages = 55296

__global__ void __launch_bounds__(256, 2) out_kernel(float* __restrict__ Out) {
    extern __shared__ unsigned short sm[];
    const unsigned sbase = (unsigned)__cvta_generic_to_shared(sm);

    const int b = blockIdx.z, s0 = blockIdx.y * 128, hg = blockIdx.x * OTILES;
    const int tid = threadIdx.x;

    auto stageA = [&]() {
        const unsigned short* gh = g_Fs + ((long)(b * SS + s0)) * RR;
#pragma unroll
        for (int p = 0; p < 4; ++p) {
            int idx = tid + p * 256;
            int r = idx >> 3, c = (idx & 7) * 8;
            cp16(sbase + (unsigned)((r * OAP + c) * 2), gh + r * RR + c);
        }
    };
    auto stageB = [&](int ht, int s) {
        const unsigned short* gh = g_Fh + ((long)(b * HH + ht * 128)) * RR;
        const unsigned base = sbase + (unsigned)((1 + s) * OBUF_B);
#pragma unroll
        for (int p = 0; p < 4; ++p) {
            int idx = tid + p * 256;
            int r = idx >> 3, c = (idx & 7) * 8;
            cp16(base + (unsigned)((r * OAP + c) * 2), gh + r * RR + c);
        }
    };

    stageA(); stageB(hg + 0, 0); cp_commit();   // group 0
    stageB(hg + 1, 1); cp_commit();             // group 1

    const int warpId = tid >> 5, lane = tid & 31;
    const int mB = (warpId >> 2) * 64, nB = (warpId & 3) * 32;
    const int g = lane >> 2, q = lane & 3;

    const unsigned aoff = 2 * ((mB + (lane & 15)) * OAP + (lane >> 4) * 8);
    const unsigned aA = sbase + aoff;
    const unsigned boff = 2 * ((nB + (lane & 7) + ((lane & 16) >> 1)) * OAP + (lane & 8));

#pragma unroll 1
    for (int j = 0; j < OTILES; ++j) {
        if (j < OTILES - 1) cp_wait1(); else cp_wait0();
        __syncthreads();

        const unsigned bH = sbase + (unsigned)((1 + (j & 1)) * OBUF_B) + boff;

        float acc[4][4][4];
#pragma unroll
        for (int i = 0; i < 4; ++i)
#pragma unroll
            for (int jj = 0; jj < 4; ++jj)
#pragma unroll
                for (int t = 0; t < 4; ++t) acc[i][jj][t] = 0.0f;

#pragma unroll
        for (int kb = 0; kb < 64; kb += 16) {
            unsigned bhf[2][4];
            ldsm4(bhf[0], bH + kb * 2);
            ldsm4(bhf[1], bH + kb * 2 + 16 * OAP * 2);
#pragma unroll
            for (int i = 0; i < 4; ++i) {
                unsigned a[4];
                ldsm4(a, aA + kb * 2 + i * (16 * OAP * 2));
#pragma unroll
                for (int jj = 0; jj < 4; ++jj)
                    mma_fp16(acc[i][jj], a, &bhf[jj >> 1][(jj & 1) * 2]);
            }
        }

        // store tile j
        float* O = Out + ((long)(b * SS + s0)) * HH + (hg + j) * 128;
#pragma unroll
        for (int i = 0; i < 4; ++i)
#pragma unroll
            for (int jj = 0; jj < 4; ++jj) {
                int r = mB + i * 16 + g;
                int c = nB + jj * 8 + 2 * q;
                *(float2*)&O[(long)r * HH + c]       = make_float2(acc[i][jj][0], acc[i][jj][1]);
                *(float2*)&O[(long)(r + 8) * HH + c] = make_float2(acc[i][jj][2], acc[i][jj][3]);
            }

        if (j + 2 < OTILES) {
            __syncthreads();
            stageB(hg + j + 2, j & 1); cp_commit();
        }
    }
}

// ---------------------------------------------------------------------------
// Launch
// ---------------------------------------------------------------------------
extern "C" void kernel_launch(void* const* d_in, const int* in_sizes, int n_in,
                              void* d_out, int out_size) {
    const float* X    = (const float*)d_in[0];
    const float* Wseq = (const float*)d_in[2];
    const float* Whid = (const float*)d_in[3];
    float* Out = (float*)d_out;

    cudaFuncSetAttribute(fact_kernel, cudaFuncAttributeMaxDynamicSharedMemorySize,
                         FSM_BYTES);
    cudaFuncSetAttribute(out_kernel, cudaFuncAttributeMaxDynamicSharedMemorySize,
                         OSM_TOT_BYTES);

    wsplit_kernel<<<128, 256>>>((const float4*)Wseq, (const float4*)Whid);
    fact_kernel<<<dim3(32, KSPLIT, BB), 256, FSM_BYTES>>>(X);
    out_kernel<<<dim3(HH / 128 / OTILES, SS / 128, BB), 256, OSM_TOT_BYTES>>>(Out);
}